// round 10
// baseline (speedup 1.0000x reference)
#include <cuda_runtime.h>
#include <math.h>

#define N_BINS 1024
#define NMASK  (N_BINS - 1)
#define DIM    512
#define DIM4   128            // float4 per row
#define NSTEPS 240
#define NK     122            // lags k in [-61, 60]
#define TI     8              // bins per tile
#define TILES  (N_BINS / TI)  // 128 tiles
#define KH     2              // K halves per tile
#define HALF4  64             // float4 per row per half
#define NCHUNK 4              // chunks of 16 float4 per half
#define CHK4   16
#define RWIN   132            // window rows 0..131 (need 1..129)
#define RPAD   133
#define NTHREADS 288          // 9 warps
#define NACT   264            // 8 groups x 33 rq
#define QBUF_F4 (CHK4 * RPAD)           // 2128 float4 per buffer
#define QBUF_BYTES (QBUF_F4 * 16)
#define DYN_BYTES (2 * QBUF_BYTES)      // 68096 B

// Scratch (device globals; no allocations allowed)
__device__ float g_x[TILES * KH * TI * 128];      // per-half X band partials
__device__ float g_stat[TILES * KH * 272];        // Q2[0,132) A[132,264) P2[264,272)
__device__ float g_bpart[NSTEPS * TILES];
__device__ unsigned g_tick[TILES];                // per-tile pair ticket
__device__ unsigned g_tick2;                      // global final ticket

union F4U2 { float4 f4; unsigned long long u[2]; };

__device__ __forceinline__ unsigned long long fma2(unsigned long long a,
                                                   unsigned long long b,
                                                   unsigned long long c) {
    unsigned long long d;
    asm("fma.rn.f32x2 %0, %1, %2, %3;" : "=l"(d) : "l"(a), "l"(b), "l"(c));
    return d;
}
__device__ __forceinline__ float unpack_sum(unsigned long long v) {
    return __uint_as_float((unsigned)(v & 0xffffffffull))
         + __uint_as_float((unsigned)(v >> 32));
}
__device__ __forceinline__ float dot4(float4 a, float4 b) {
    return a.x * b.x + a.y * b.y + a.z * b.z + a.w * b.w;
}
__device__ __forceinline__ void cp16(unsigned dst, const float4* src) {
    asm volatile("cp.async.cg.shared.global [%0], [%1], 16;" :: "r"(dst), "l"(src));
}
#define CP_COMMIT() asm volatile("cp.async.commit_group;")
#define CP_WAIT(n)  asm volatile("cp.async.wait_group %0;" :: "n"(n))

// ---------------------------------------------------------------------------
// One block = (tile, K-half). Computes partial X[t][k] band + partial stats
// over its 256 dims. Second block of each pair combines halves and evaluates
// the 240 steps; globally-last block does the argmin.
// ---------------------------------------------------------------------------
__global__ void __launch_bounds__(NTHREADS, 2)
k_main(const float* __restrict__ Dq, const float* __restrict__ Dp,
       float* __restrict__ out) {
    extern __shared__ __align__(16) float4 dynbuf[];   // 2 Q chunk buffers
    __shared__ float4 Psf[TI][HALF4];                  // 8 KB P half-tile
    __shared__ float  Xs[TI][128];
    __shared__ float  sQ2[RWIN], sA[RWIN], sP2[TI];
    __shared__ unsigned long long wk[NTHREADS / 32];
    __shared__ bool s_sec, s_last;

    float* Sp = (float*)dynbuf;      // [2][4][132] stats partials
    float* Cp = (float*)dynbuf;      // [4][8][132] X partials

    const int tile = blockIdx.x;
    const int kh   = blockIdx.y;
    const int i0   = tile * TI;
    const int tid  = threadIdx.x;
    const int lane = tid & 31;
    const int warp = tid >> 5;
    const int khoff = kh * HALF4;    // float4 column offset of this half

    const bool act = (tid < NACT);
    const int  rq  = act ? (tid % 33) : 0;
    const int  grp = act ? (tid / 33) : 0;   // 0..7
    const int  tg  = grp & 1;                // t in [4tg, 4tg+4)
    const int  kc  = grp >> 1;               // 4 l-slots: l = 4kc + j2
    const int  rqm1_0 = (rq == 0) ? 0 : (rq - 1);

    const float4* P4 = (const float4*)Dp;
    const float4* Q4 = (const float4*)Dq;
    const unsigned sb = (unsigned)__cvta_generic_to_shared(dynbuf);

    // ---- loader assignment: 2112 copies/chunk over 288 threads ----------
    int goff[8], slot[8]; unsigned vmask = 0;
    #pragma unroll
    for (int p = 0; p < 8; p++) {
        int idx = tid + NTHREADS * p;
        if (idx < CHK4 * RWIN) {
            vmask |= (1u << p);
            int l = idx / RWIN, r = idx - l * RWIN;
            int j = (i0 - 61 + r) & NMASK;
            goff[p] = j * DIM4 + khoff + l;         // + c*CHK4 per chunk
            slot[p] = l * RPAD + r;
        } else { goff[p] = 0; slot[p] = 0; }
    }

    // ---- P half-tile + P2 partial ---------------------------------------
    for (int idx = tid; idx < TI * HALF4; idx += NTHREADS) {
        int t = idx >> 6, cgl = idx & 63;
        ((float4*)Psf)[idx] = P4[(i0 + t) * DIM4 + khoff + cgl];
    }
    // issue chunk 0 and 1 while P2 computes
    #pragma unroll
    for (int p = 0; p < 8; p++)
        if (vmask & (1u << p)) cp16(sb + slot[p] * 16, Q4 + goff[p]);
    CP_COMMIT();
    #pragma unroll
    for (int p = 0; p < 8; p++)
        if (vmask & (1u << p)) cp16(sb + QBUF_BYTES + slot[p] * 16, Q4 + goff[p] + CHK4);
    CP_COMMIT();
    __syncthreads();               // Psf visible
    if (warp < TI) {
        float4 p0 = Psf[warp][lane], p1 = Psf[warp][lane + 32];
        float s = dot4(p0, p0) + dot4(p1, p1);
        #pragma unroll
        for (int off = 16; off; off >>= 1) s += __shfl_xor_sync(0xffffffffu, s, off);
        if (lane == 0) g_stat[(tile * KH + kh) * 272 + 264 + warp] = s;
    }
    CP_WAIT(1);                    // chunk 0 ready
    __syncthreads();

    // ---- accumulators ----------------------------------------------------
    unsigned long long acc2[4][4];
    #pragma unroll
    for (int a = 0; a < 4; a++)
        #pragma unroll
        for (int b = 0; b < 4; b++) acc2[a][b] = 0ull;
    unsigned long long q2a2[4] = {0ull,0ull,0ull,0ull};
    unsigned long long aaa2[4] = {0ull,0ull,0ull,0ull};

    // ---- chunk loop (4 chunks, double-buffered cp.async) -----------------
    #pragma unroll
    for (int c = 0; c < NCHUNK; c++) {
        if (act) {
            const float4* Qb = dynbuf + (c & 1) * QBUF_F4;
            #pragma unroll
            for (int j2 = 0; j2 < 4; j2++) {
                const int l = 4 * kc + j2;
                const float4* qb = Qb + l * RPAD;
                F4U2 qv[4];
                qv[0].f4 = qb[rq];       qv[1].f4 = qb[rq + 33];
                qv[2].f4 = qb[rq + 66];  qv[3].f4 = qb[rq + 99];
                F4U2 pv[4];
                #pragma unroll
                for (int tt = 0; tt < 4; tt++)
                    pv[tt].f4 = Psf[tg * 4 + tt][c * CHK4 + l];
                #pragma unroll
                for (int tt = 0; tt < 4; tt++)
                    #pragma unroll
                    for (int m = 0; m < 4; m++) {
                        acc2[tt][m] = fma2(qv[m].u[0], pv[tt].u[0], acc2[tt][m]);
                        acc2[tt][m] = fma2(qv[m].u[1], pv[tt].u[1], acc2[tt][m]);
                    }
                if (tg == 0) {
                    F4U2 pq0, pq1, pq2, pq3;
                    pq0.f4 = qb[rqm1_0];   pq1.f4 = qb[rq + 32];
                    pq2.f4 = qb[rq + 65];  pq3.f4 = qb[rq + 98];
                    #pragma unroll
                    for (int m = 0; m < 4; m++) {
                        q2a2[m] = fma2(qv[m].u[0], qv[m].u[0], q2a2[m]);
                        q2a2[m] = fma2(qv[m].u[1], qv[m].u[1], q2a2[m]);
                    }
                    aaa2[0] = fma2(qv[0].u[0], pq0.u[0], aaa2[0]);
                    aaa2[0] = fma2(qv[0].u[1], pq0.u[1], aaa2[0]);
                    aaa2[1] = fma2(qv[1].u[0], pq1.u[0], aaa2[1]);
                    aaa2[1] = fma2(qv[1].u[1], pq1.u[1], aaa2[1]);
                    aaa2[2] = fma2(qv[2].u[0], pq2.u[0], aaa2[2]);
                    aaa2[2] = fma2(qv[2].u[1], pq2.u[1], aaa2[2]);
                    aaa2[3] = fma2(qv[3].u[0], pq3.u[0], aaa2[3]);
                    aaa2[3] = fma2(qv[3].u[1], pq3.u[1], aaa2[3]);
                }
            }
        }
        __syncthreads();           // done reading buf (c&1); safe to overwrite
        if (c + 2 < NCHUNK) {
            #pragma unroll
            for (int p = 0; p < 8; p++)
                if (vmask & (1u << p))
                    cp16(sb + (c & 1) * QBUF_BYTES + slot[p] * 16,
                         Q4 + goff[p] + (c + 2) * CHK4);
            CP_COMMIT();
            CP_WAIT(1);            // chunk c+1 done (c+2 may be pending)
            __syncthreads();
        } else if (c + 1 < NCHUNK) {
            CP_WAIT(0);            // chunk c+1 done
            __syncthreads();
        }
    }

    const int gsb = (tile * KH + kh) * 272;
    // ---- stats: kc-reduce -> g_stat -------------------------------------
    if (act && tg == 0) {
        #pragma unroll
        for (int m = 0; m < 4; m++) {
            int r = rq + 33 * m;
            Sp[0 * 528 + kc * RWIN + r] = unpack_sum(q2a2[m]);
            Sp[1 * 528 + kc * RWIN + r] = unpack_sum(aaa2[m]);
        }
    }
    __syncthreads();
    if (tid < 2 * RWIN) {
        int a = (tid >= RWIN) ? 1 : 0;
        int r = tid - a * RWIN;
        const float* base = Sp + a * 528 + r;
        float s = base[0] + base[RWIN] + base[2 * RWIN] + base[3 * RWIN];
        g_stat[gsb + a * RWIN + r] = s;
    }
    __syncthreads();   // Sp consumed; reuse as Cp

    // ---- X: kc-reduce -> g_x --------------------------------------------
    if (act) {
        #pragma unroll
        for (int tt = 0; tt < 4; tt++)
            #pragma unroll
            for (int m = 0; m < 4; m++)
                Cp[kc * 1056 + (tg * 4 + tt) * RWIN + (rq + 33 * m)] =
                    unpack_sum(acc2[tt][m]);
    }
    __syncthreads();
    {
        float* gx = g_x + (tile * KH + kh) * (TI * 128);
        for (int o = tid; o < TI * RWIN; o += NTHREADS) {
            int t = o / RWIN, r = o - t * RWIN;
            const float* base = Cp + t * RWIN + r;
            float x = base[0] + base[1056] + base[2112] + base[3168];
            int kk = t + 122 - r;
            if ((unsigned)kk < (unsigned)NK) gx[t * 128 + kk] = x;
        }
    }

    // ---- pair ticket: second block of this tile combines -----------------
    __threadfence();
    __syncthreads();
    if (tid == 0) {
        unsigned t = atomicAdd(&g_tick[tile], 1u);
        s_sec = (t == 1u);
        if (s_sec) g_tick[tile] = 0;   // reset for replay
    }
    __syncthreads();
    if (!s_sec) return;

    // combine halves (fixed order: half0 + half1 -> deterministic)
    {
        const float* g0 = g_stat + (tile * KH + 0) * 272;
        const float* g1 = g_stat + (tile * KH + 1) * 272;
        if (tid < 272) {
            float v = g0[tid] + g1[tid];
            if (tid < RWIN)            sQ2[tid] = v;
            else if (tid < 2 * RWIN)   sA[tid - RWIN] = v;
            else                       sP2[tid - 2 * RWIN] = v;
        }
        const float* x0 = g_x + (tile * KH + 0) * (TI * 128);
        const float* x1 = g_x + (tile * KH + 1) * (TI * 128);
        float* Xf = &Xs[0][0];
        for (int o = tid; o < TI * 128; o += NTHREADS) Xf[o] = x0[o] + x1[o];
    }
    __syncthreads();

    // ---- Phase 3: evaluate 240 steps ------------------------------------
    if (tid < NSTEPS) {
        const int s = tid;
        int k0, k1; float alpha; bool pos;
        if (s < 120) {                         // 0.0, 0.5, ..., 59.5
            k0 = s >> 1; k1 = k0 + 1;
            alpha = (s & 1) ? 0.5f : 0.0f;
            pos = true;
        } else {                               // -1.0, -1.5, ..., -60.5
            int u = s - 120;
            k0 = -(1 + (u >> 1)); k1 = k0 - 1;
            alpha = (u & 1) ? 0.5f : 0.0f;
            pos = false;
        }
        const float w0 = 1.0f - alpha, w1 = alpha;
        const float w00 = w0 * w0, w11 = w1 * w1, w01 = 2.0f * w0 * w1;
        float accs = 0.0f;
        #pragma unroll
        for (int t = 0; t < TI; t++) {
            int j0r = t + 61 - k0;
            int j1r = t + 61 - k1;
            float adot = pos ? sA[j0r] : sA[j1r];
            float x0 = Xs[t][k0 + 61];
            float x1 = Xs[t][k1 + 61];
            float r2 = sP2[t] + w00 * sQ2[j0r] + w11 * sQ2[j1r]
                     + w01 * adot - 2.0f * (w0 * x0 + w1 * x1);
            accs += sqrtf(fmaxf(r2, 0.0f));
        }
        g_bpart[s * TILES + tile] = accs;
    }

    // ---- global ticket: last combiner does the argmin --------------------
    __threadfence();
    __syncthreads();
    if (tid == 0) {
        unsigned t = atomicAdd(&g_tick2, 1u);
        s_last = (t == (unsigned)(TILES - 1));
        if (s_last) g_tick2 = 0;
    }
    __syncthreads();
    if (!s_last) return;

    unsigned long long key = ~0ull;
    if (tid < NSTEPS) {
        const float4* bp = (const float4*)(g_bpart + tid * TILES);
        float s0 = 0.f, s1 = 0.f, s2 = 0.f, s3 = 0.f;
        #pragma unroll
        for (int c = 0; c < TILES / 4; c += 4) {
            float4 v0 = bp[c], v1 = bp[c + 1], v2 = bp[c + 2], v3 = bp[c + 3];
            s0 += v0.x + v0.y + v0.z + v0.w;
            s1 += v1.x + v1.y + v1.z + v1.w;
            s2 += v2.x + v2.y + v2.z + v2.w;
            s3 += v3.x + v3.y + v3.z + v3.w;
        }
        float dist = ((s0 + s1) + (s2 + s3)) * (1.0f / (float)N_BINS);
        key = ((unsigned long long)__float_as_uint(dist) << 32) | (unsigned)tid;
    }
    #pragma unroll
    for (int off = 16; off; off >>= 1) {
        unsigned long long o = __shfl_xor_sync(0xffffffffu, key, off);
        if (o < key) key = o;
    }
    if (lane == 0) wk[warp] = key;
    __syncthreads();
    if (tid == 0) {
        unsigned long long best = wk[0];
        #pragma unroll
        for (int w = 1; w < NTHREADS / 32; w++) if (wk[w] < best) best = wk[w];
        int bi = (int)(best & 0xffffffffull);
        float dist = __uint_as_float((unsigned)(best >> 32));
        float step = (bi < 120) ? 0.5f * (float)bi : -(1.0f + 0.5f * (float)(bi - 120));
        out[0] = step;
        out[1] = dist;
    }
}

extern "C" void kernel_launch(void* const* d_in, const int* in_sizes, int n_in,
                              void* d_out, int out_size) {
    const float* Dq = (const float*)d_in[0];  // D_q [1024, 512]
    const float* Dp = (const float*)d_in[1];  // D_p [1024, 512]
    float* out = (float*)d_out;

    cudaFuncSetAttribute(k_main, cudaFuncAttributeMaxDynamicSharedMemorySize,
                         DYN_BYTES);
    dim3 grid(TILES, KH);
    k_main<<<grid, NTHREADS, DYN_BYTES>>>(Dq, Dp, out);
}

// round 11
// speedup vs baseline: 1.4660x; 1.4660x over previous
#include <cuda_runtime.h>
#include <math.h>

#define N_BINS 1024
#define NMASK  (N_BINS - 1)
#define DIM    512
#define DIM4   128            // DIM / 4 (float4 units)
#define NSTEPS 240
#define NK     122            // lags k in [-61, 60]
#define TI     8              // bins per block
#define NBLK   (N_BINS / TI)  // 128 blocks
#define NTHREADS 768
#define NWARPS   24
#define ROWS_PER_WARP 6       // window rows 0..128 covered by 24 warps

// Scratch (device globals; no allocations allowed)
__device__ float g_bpart[NSTEPS * NBLK];   // per-(step, block) partial sums
__device__ unsigned g_ticket;              // last-block election (reset each launch)

__device__ __forceinline__ float dot4(float4 a, float4 b) {
    return a.x * b.x + a.y * b.y + a.z * b.z + a.w * b.w;
}

// ---------------------------------------------------------------------------
// k_main: one block per 8-bin tile (structure proven in R4; 24 warps).
//   Phase 1: load 8 D_p rows to smem, compute |P|^2 per bin.
//   Phase 2: stream the Q window (rows 0..128 rel. to i0-60), 2-row batches
//            per warp, barrier-free; produce banded X-corr + row stats.
//   Phase 3: evaluate all 240 fractional steps, emit per-block partial sums.
//   Phase 4: last block (atomic ticket) -> mean dist -> argmin -> out.
// ---------------------------------------------------------------------------
__global__ void __launch_bounds__(NTHREADS) k_main(const float* __restrict__ Dq,
                                                   const float* __restrict__ Dp,
                                                   float* __restrict__ out) {
    __shared__ float4 Ps[TI][DIM4];  // 16 KB
    __shared__ float  Xs[TI][128];   // 4 KB, index kk = k + 61 in [0,121]
    __shared__ float  sQ2[136];      // window rows 0..128 used
    __shared__ float  sA[136];
    __shared__ float  sP2[TI];

    const int i0   = blockIdx.x * TI;
    const int tid  = threadIdx.x;
    const int warp = tid >> 5;
    const int lane = tid & 31;

    const float4* P4 = (const float4*)Dp;
    const float4* Q4 = (const float4*)Dq;

    // ---- Phase 1: P rows to smem --------------------------------------
    for (int idx = tid; idx < TI * DIM4; idx += NTHREADS) {
        int t = idx >> 7, c = idx & 127;
        Ps[t][c] = P4[(i0 + t) * DIM4 + c];
    }
    __syncthreads();

    if (warp < TI) {  // warp w -> |P[i0+w]|^2
        float4 p0 = Ps[warp][lane], p1 = Ps[warp][lane + 32],
               p2 = Ps[warp][lane + 64], p3 = Ps[warp][lane + 96];
        float s = dot4(p0, p0) + dot4(p1, p1) + dot4(p2, p2) + dot4(p3, p3);
        #pragma unroll
        for (int off = 16; off; off >>= 1) s += __shfl_xor_sync(0xffffffffu, s, off);
        if (lane == 0) sP2[warp] = s;
    }

    // ---- Phase 2: Q window streaming (barrier-free) --------------------
    // Warp w covers rows [6w, 6w+6); rows > 128 are guarded out.
    // prev = row 6w-1 seeds the A chain.
    {
        const int base = ROWS_PER_WARP * warp;
        const float4* qp = Q4 + (((i0 - 61 + base) & NMASK) * DIM4);  // row base-1
        float4 pv0 = qp[lane], pv1 = qp[lane + 32], pv2 = qp[lane + 64], pv3 = qp[lane + 96];

        #pragma unroll
        for (int m = 0; m < 3; m++) {
            const int ra = base + 2 * m;
            if (ra <= 128) {
                const int rb = ra + 1;
                const float4* qa = Q4 + (((i0 - 60 + ra) & NMASK) * DIM4);
                const float4* qb = Q4 + (((i0 - 60 + rb) & NMASK) * DIM4);
                float4 a0 = qa[lane], a1 = qa[lane + 32], a2 = qa[lane + 64], a3 = qa[lane + 96];
                float4 b0 = qb[lane], b1 = qb[lane + 32], b2 = qb[lane + 64], b3 = qb[lane + 96];

                // stats (free: rows already in regs)
                float q2a = dot4(a0, a0) + dot4(a1, a1) + dot4(a2, a2) + dot4(a3, a3);
                float q2b = dot4(b0, b0) + dot4(b1, b1) + dot4(b2, b2) + dot4(b3, b3);
                float aa  = dot4(a0, pv0) + dot4(a1, pv1) + dot4(a2, pv2) + dot4(a3, pv3);
                float ab  = dot4(b0, a0) + dot4(b1, a1) + dot4(b2, a2) + dot4(b3, a3);

                // cross-corr accumulators: v[2t] = row ra vs bin t, v[2t+1] = row rb
                float v[2 * TI];
                #pragma unroll
                for (int t = 0; t < TI; t++) {
                    float4 p0 = Ps[t][lane], p1 = Ps[t][lane + 32],
                           p2 = Ps[t][lane + 64], p3 = Ps[t][lane + 96];
                    v[2 * t]     = dot4(a0, p0) + dot4(a1, p1) + dot4(a2, p2) + dot4(a3, p3);
                    v[2 * t + 1] = dot4(b0, p0) + dot4(b1, p1) + dot4(b2, p2) + dot4(b3, p3);
                }

                // ---- folded multi-array reduction: 16 arrays over 32 lanes.
                float r8[8];
                #pragma unroll
                for (int i = 0; i < 8; i++) {
                    bool hi = (lane & 16) != 0;
                    float mine  = hi ? v[2 * i + 1] : v[2 * i];
                    float other = hi ? v[2 * i]     : v[2 * i + 1];
                    r8[i] = mine + __shfl_xor_sync(0xffffffffu, other, 16);
                }
                float r4[4];
                #pragma unroll
                for (int i = 0; i < 4; i++) {
                    bool hi = (lane & 8) != 0;
                    float mine  = hi ? r8[2 * i + 1] : r8[2 * i];
                    float other = hi ? r8[2 * i]     : r8[2 * i + 1];
                    r4[i] = mine + __shfl_xor_sync(0xffffffffu, other, 8);
                }
                float r2a[2];
                #pragma unroll
                for (int i = 0; i < 2; i++) {
                    bool hi = (lane & 4) != 0;
                    float mine  = hi ? r4[2 * i + 1] : r4[2 * i];
                    float other = hi ? r4[2 * i]     : r4[2 * i + 1];
                    r2a[i] = mine + __shfl_xor_sync(0xffffffffu, other, 4);
                }
                float r1;
                {
                    bool hi = (lane & 2) != 0;
                    float mine  = hi ? r2a[1] : r2a[0];
                    float other = hi ? r2a[0] : r2a[1];
                    r1 = mine + __shfl_xor_sync(0xffffffffu, other, 2);
                }
                r1 += __shfl_xor_sync(0xffffffffu, r1, 1);
                if (!(lane & 1)) {
                    int g   = ((lane >> 4) & 1) | (((lane >> 3) & 1) << 1)
                            | (((lane >> 2) & 1) << 2) | (((lane >> 1) & 1) << 3);
                    int t   = g >> 1;
                    int row = (g & 1) ? rb : ra;
                    int kk  = t + 121 - row;   // k + 61
                    if (kk >= 0 && kk < NK) Xs[t][kk] = r1;
                }

                // ---- stats reduction: 4 arrays (q2a,q2b,aa,ab)
                float s1;
                {
                    bool hi = (lane & 16) != 0;
                    float m0 = hi ? q2b : q2a, o0 = hi ? q2a : q2b;
                    float m1 = hi ? ab  : aa,  o1 = hi ? aa  : ab;
                    float u0 = m0 + __shfl_xor_sync(0xffffffffu, o0, 16);
                    float u1 = m1 + __shfl_xor_sync(0xffffffffu, o1, 16);
                    bool h2 = (lane & 8) != 0;
                    float mm = h2 ? u1 : u0, oo = h2 ? u0 : u1;
                    s1 = mm + __shfl_xor_sync(0xffffffffu, oo, 8);
                }
                s1 += __shfl_xor_sync(0xffffffffu, s1, 4);
                s1 += __shfl_xor_sync(0xffffffffu, s1, 2);
                s1 += __shfl_xor_sync(0xffffffffu, s1, 1);
                if (lane == 0)  sQ2[ra] = s1;
                if (lane == 16 && rb <= 128) sQ2[rb] = s1;
                if (lane == 8)  sA[ra]  = s1;
                if (lane == 24 && rb <= 128) sA[rb]  = s1;

                pv0 = b0; pv1 = b1; pv2 = b2; pv3 = b3;
            }
        }
    }
    __syncthreads();

    // ---- Phase 3: evaluate 240 steps over this block's 8 bins ----------
    if (tid < NSTEPS) {
        const int s = tid;
        int k0, k1; float alpha; bool pos;
        if (s < 120) {                         // steps 0.0, 0.5, ..., 59.5
            k0 = s >> 1; k1 = k0 + 1;
            alpha = (s & 1) ? 0.5f : 0.0f;
            pos = true;
        } else {                               // steps -1.0, -1.5, ..., -60.5
            int u = s - 120;
            k0 = -(1 + (u >> 1)); k1 = k0 - 1;
            alpha = (u & 1) ? 0.5f : 0.0f;
            pos = false;
        }
        const float w0 = 1.0f - alpha, w1 = alpha;
        const float w00 = w0 * w0, w11 = w1 * w1, w01 = 2.0f * w0 * w1;
        float acc = 0.0f;
        #pragma unroll
        for (int t = 0; t < TI; t++) {
            int j0r = t + 60 - k0;             // window-relative row of roll k0
            int j1r = t + 60 - k1;
            float adot = pos ? sA[j0r] : sA[j1r];   // Q[j0].Q[j1] adjacency
            float x0 = Xs[t][k0 + 61];
            float x1 = Xs[t][k1 + 61];
            float r2 = sP2[t] + w00 * sQ2[j0r] + w11 * sQ2[j1r]
                     + w01 * adot - 2.0f * (w0 * x0 + w1 * x1);
            acc += sqrtf(fmaxf(r2, 0.0f));
        }
        g_bpart[s * NBLK + blockIdx.x] = acc;
    }

    // ---- Phase 4: last block reduces everything (no second launch) -----
    __threadfence();
    __shared__ bool is_last;
    __syncthreads();                 // all phase-3 stores of this block issued
    if (tid == 0) {
        unsigned t = atomicAdd(&g_ticket, 1u);
        is_last = (t == (unsigned)(NBLK - 1));
        if (is_last) g_ticket = 0;   // reset for next graph replay
    }
    __syncthreads();
    if (!is_last) return;

    // Deterministic mean + argmin (identical summation order every launch).
    const int s    = tid >> 1;       // 2 threads per step, 64 partials each
    const int half = tid & 1;
    unsigned long long key = ~0ull;
    if (s < NSTEPS) {
        const float4* bp = (const float4*)(g_bpart + s * NBLK + half * (NBLK / 2));
        float s0 = 0.f, s1 = 0.f, s2 = 0.f, s3 = 0.f;
        #pragma unroll
        for (int c = 0; c < NBLK / 8; c += 4) {
            float4 v0 = bp[c], v1 = bp[c + 1], v2 = bp[c + 2], v3 = bp[c + 3];
            s0 += v0.x + v0.y + v0.z + v0.w;
            s1 += v1.x + v1.y + v1.z + v1.w;
            s2 += v2.x + v2.y + v2.z + v2.w;
            s3 += v3.x + v3.y + v3.z + v3.w;
        }
        float mine = (s0 + s1) + (s2 + s3);
        float tot  = mine + __shfl_xor_sync(0xffffffffu, mine, 1);
        float dist = tot * (1.0f / (float)N_BINS);
        // positive-float bit order == numeric order; low 32 bits = index so
        // ties resolve to the smallest step index (matches jnp.argmin).
        key = ((unsigned long long)__float_as_uint(dist) << 32) | (unsigned)s;
    }
    #pragma unroll
    for (int off = 16; off; off >>= 1) {
        unsigned long long o = __shfl_xor_sync(0xffffffffu, key, off);
        if (o < key) key = o;
    }
    __shared__ unsigned long long wk[NWARPS];
    if (lane == 0) wk[warp] = key;
    __syncthreads();
    if (tid == 0) {
        unsigned long long best = wk[0];
        #pragma unroll
        for (int w = 1; w < NWARPS; w++) if (wk[w] < best) best = wk[w];
        int bi = (int)(best & 0xffffffffull);
        float dist = __uint_as_float((unsigned)(best >> 32));
        float step = (bi < 120) ? 0.5f * (float)bi : -(1.0f + 0.5f * (float)(bi - 120));
        out[0] = step;
        out[1] = dist;
    }
}

extern "C" void kernel_launch(void* const* d_in, const int* in_sizes, int n_in,
                              void* d_out, int out_size) {
    const float* Dq = (const float*)d_in[0];  // D_q [1024, 512]
    const float* Dp = (const float*)d_in[1];  // D_p [1024, 512]
    float* out = (float*)d_out;

    k_main<<<NBLK, NTHREADS>>>(Dq, Dp, out);
}

// round 12
// speedup vs baseline: 1.4681x; 1.0014x over previous
#include <cuda_runtime.h>
#include <math.h>

#define N_BINS 1024
#define NMASK  (N_BINS - 1)
#define DIM    512
#define DIM4   128            // DIM / 4 (float4 units)
#define NSTEPS 240
#define NK     122            // lags k in [-61, 60]
#define TI     8              // bins per block
#define NBLK   (N_BINS / TI)  // 128 blocks
#define NTHREADS 768
#define NWARPS   24
#define ROWS_PER_WARP 6       // window rows 0..128 covered by 24 warps

// Scratch (device globals; no allocations allowed)
__device__ float g_bpart[NSTEPS * NBLK];   // per-(step, block) partial sums
__device__ unsigned g_ticket;              // last-block election (reset each launch)

union F4U2 { float4 f4; unsigned long long u[2]; };

__device__ __forceinline__ unsigned long long fma2(unsigned long long a,
                                                   unsigned long long b,
                                                   unsigned long long c) {
    unsigned long long d;
    asm("fma.rn.f32x2 %0, %1, %2, %3;" : "=l"(d) : "l"(a), "l"(b), "l"(c));
    return d;
}
__device__ __forceinline__ unsigned long long dot4x2(const F4U2& x, const F4U2& y,
                                                     unsigned long long acc) {
    acc = fma2(x.u[0], y.u[0], acc);
    acc = fma2(x.u[1], y.u[1], acc);
    return acc;
}
__device__ __forceinline__ float unpack_sum(unsigned long long v) {
    return __uint_as_float((unsigned)(v & 0xffffffffull))
         + __uint_as_float((unsigned)(v >> 32));
}
__device__ __forceinline__ float dot4(float4 a, float4 b) {
    return a.x * b.x + a.y * b.y + a.z * b.z + a.w * b.w;
}

// ---------------------------------------------------------------------------
// k_main: one block per 8-bin tile (structure proven in R4/R11; 24 warps).
//   Phase 1: load 8 D_p rows to smem, compute |P|^2 per bin.
//   Phase 2: stream the Q window (rows 0..128 rel. to i0-60), 2-row batches
//            per warp, barrier-free; dot products in packed f32x2 (FFMA2).
//   Phase 3: evaluate all 240 fractional steps, emit per-block partial sums.
//   Phase 4: last block (atomic ticket) -> mean dist -> argmin -> out.
// ---------------------------------------------------------------------------
__global__ void __launch_bounds__(NTHREADS) k_main(const float* __restrict__ Dq,
                                                   const float* __restrict__ Dp,
                                                   float* __restrict__ out) {
    __shared__ float4 Ps[TI][DIM4];  // 16 KB
    __shared__ float  Xs[TI][128];   // 4 KB, index kk = k + 61 in [0,121]
    __shared__ float  sQ2[136];      // window rows 0..128 used
    __shared__ float  sA[136];
    __shared__ float  sP2[TI];

    const int i0   = blockIdx.x * TI;
    const int tid  = threadIdx.x;
    const int warp = tid >> 5;
    const int lane = tid & 31;

    const float4* P4 = (const float4*)Dp;
    const float4* Q4 = (const float4*)Dq;

    // ---- Phase 1: P rows to smem --------------------------------------
    for (int idx = tid; idx < TI * DIM4; idx += NTHREADS) {
        int t = idx >> 7, c = idx & 127;
        Ps[t][c] = P4[(i0 + t) * DIM4 + c];
    }
    __syncthreads();

    if (warp < TI) {  // warp w -> |P[i0+w]|^2
        float4 p0 = Ps[warp][lane], p1 = Ps[warp][lane + 32],
               p2 = Ps[warp][lane + 64], p3 = Ps[warp][lane + 96];
        float s = dot4(p0, p0) + dot4(p1, p1) + dot4(p2, p2) + dot4(p3, p3);
        #pragma unroll
        for (int off = 16; off; off >>= 1) s += __shfl_xor_sync(0xffffffffu, s, off);
        if (lane == 0) sP2[warp] = s;
    }

    // ---- Phase 2: Q window streaming (barrier-free, packed FMA) --------
    // Warp w covers rows [6w, 6w+6); rows > 128 are guarded out.
    // prev = row 6w-1 seeds the A chain.
    {
        const int base = ROWS_PER_WARP * warp;
        const float4* qp = Q4 + (((i0 - 61 + base) & NMASK) * DIM4);  // row base-1
        F4U2 pv0, pv1, pv2, pv3;
        pv0.f4 = qp[lane]; pv1.f4 = qp[lane + 32];
        pv2.f4 = qp[lane + 64]; pv3.f4 = qp[lane + 96];

        #pragma unroll
        for (int m = 0; m < 3; m++) {
            const int ra = base + 2 * m;
            if (ra <= 128) {
                const int rb = ra + 1;
                const float4* qa = Q4 + (((i0 - 60 + ra) & NMASK) * DIM4);
                const float4* qb = Q4 + (((i0 - 60 + rb) & NMASK) * DIM4);
                F4U2 a0, a1, a2, a3, b0, b1, b2, b3;
                a0.f4 = qa[lane]; a1.f4 = qa[lane + 32];
                a2.f4 = qa[lane + 64]; a3.f4 = qa[lane + 96];
                b0.f4 = qb[lane]; b1.f4 = qb[lane + 32];
                b2.f4 = qb[lane + 64]; b3.f4 = qb[lane + 96];

                // stats (packed): |a|^2, |b|^2, a.prev, b.a
                float q2a, q2b, aa, ab;
                {
                    unsigned long long s;
                    s = dot4x2(a0, a0, 0ull); s = dot4x2(a1, a1, s);
                    s = dot4x2(a2, a2, s);    s = dot4x2(a3, a3, s);
                    q2a = unpack_sum(s);
                    s = dot4x2(b0, b0, 0ull); s = dot4x2(b1, b1, s);
                    s = dot4x2(b2, b2, s);    s = dot4x2(b3, b3, s);
                    q2b = unpack_sum(s);
                    s = dot4x2(a0, pv0, 0ull); s = dot4x2(a1, pv1, s);
                    s = dot4x2(a2, pv2, s);    s = dot4x2(a3, pv3, s);
                    aa = unpack_sum(s);
                    s = dot4x2(b0, a0, 0ull); s = dot4x2(b1, a1, s);
                    s = dot4x2(b2, a2, s);    s = dot4x2(b3, a3, s);
                    ab = unpack_sum(s);
                }

                // cross-corr: v[2t] = a.P[t], v[2t+1] = b.P[t]  (packed)
                float v[2 * TI];
                #pragma unroll
                for (int t = 0; t < TI; t++) {
                    F4U2 p0, p1, p2, p3;
                    p0.f4 = Ps[t][lane];      p1.f4 = Ps[t][lane + 32];
                    p2.f4 = Ps[t][lane + 64]; p3.f4 = Ps[t][lane + 96];
                    unsigned long long va, vb;
                    va = dot4x2(a0, p0, 0ull); va = dot4x2(a1, p1, va);
                    va = dot4x2(a2, p2, va);   va = dot4x2(a3, p3, va);
                    vb = dot4x2(b0, p0, 0ull); vb = dot4x2(b1, p1, vb);
                    vb = dot4x2(b2, p2, vb);   vb = dot4x2(b3, p3, vb);
                    v[2 * t]     = unpack_sum(va);
                    v[2 * t + 1] = unpack_sum(vb);
                }

                // ---- folded multi-array reduction: 16 arrays over 32 lanes.
                float r8[8];
                #pragma unroll
                for (int i = 0; i < 8; i++) {
                    bool hi = (lane & 16) != 0;
                    float mine  = hi ? v[2 * i + 1] : v[2 * i];
                    float other = hi ? v[2 * i]     : v[2 * i + 1];
                    r8[i] = mine + __shfl_xor_sync(0xffffffffu, other, 16);
                }
                float r4[4];
                #pragma unroll
                for (int i = 0; i < 4; i++) {
                    bool hi = (lane & 8) != 0;
                    float mine  = hi ? r8[2 * i + 1] : r8[2 * i];
                    float other = hi ? r8[2 * i]     : r8[2 * i + 1];
                    r4[i] = mine + __shfl_xor_sync(0xffffffffu, other, 8);
                }
                float r2a[2];
                #pragma unroll
                for (int i = 0; i < 2; i++) {
                    bool hi = (lane & 4) != 0;
                    float mine  = hi ? r4[2 * i + 1] : r4[2 * i];
                    float other = hi ? r4[2 * i]     : r4[2 * i + 1];
                    r2a[i] = mine + __shfl_xor_sync(0xffffffffu, other, 4);
                }
                float r1;
                {
                    bool hi = (lane & 2) != 0;
                    float mine  = hi ? r2a[1] : r2a[0];
                    float other = hi ? r2a[0] : r2a[1];
                    r1 = mine + __shfl_xor_sync(0xffffffffu, other, 2);
                }
                r1 += __shfl_xor_sync(0xffffffffu, r1, 1);
                if (!(lane & 1)) {
                    int g   = ((lane >> 4) & 1) | (((lane >> 3) & 1) << 1)
                            | (((lane >> 2) & 1) << 2) | (((lane >> 1) & 1) << 3);
                    int t   = g >> 1;
                    int row = (g & 1) ? rb : ra;
                    int kk  = t + 121 - row;   // k + 61
                    if (kk >= 0 && kk < NK) Xs[t][kk] = r1;
                }

                // ---- stats reduction: 4 arrays (q2a,q2b,aa,ab)
                float s1;
                {
                    bool hi = (lane & 16) != 0;
                    float m0 = hi ? q2b : q2a, o0 = hi ? q2a : q2b;
                    float m1 = hi ? ab  : aa,  o1 = hi ? aa  : ab;
                    float u0 = m0 + __shfl_xor_sync(0xffffffffu, o0, 16);
                    float u1 = m1 + __shfl_xor_sync(0xffffffffu, o1, 16);
                    bool h2 = (lane & 8) != 0;
                    float mm = h2 ? u1 : u0, oo = h2 ? u0 : u1;
                    s1 = mm + __shfl_xor_sync(0xffffffffu, oo, 8);
                }
                s1 += __shfl_xor_sync(0xffffffffu, s1, 4);
                s1 += __shfl_xor_sync(0xffffffffu, s1, 2);
                s1 += __shfl_xor_sync(0xffffffffu, s1, 1);
                if (lane == 0)  sQ2[ra] = s1;
                if (lane == 16 && rb <= 128) sQ2[rb] = s1;
                if (lane == 8)  sA[ra]  = s1;
                if (lane == 24 && rb <= 128) sA[rb]  = s1;

                pv0 = b0; pv1 = b1; pv2 = b2; pv3 = b3;
            }
        }
    }
    __syncthreads();

    // ---- Phase 3: evaluate 240 steps over this block's 8 bins ----------
    if (tid < NSTEPS) {
        const int s = tid;
        int k0, k1; float alpha; bool pos;
        if (s < 120) {                         // steps 0.0, 0.5, ..., 59.5
            k0 = s >> 1; k1 = k0 + 1;
            alpha = (s & 1) ? 0.5f : 0.0f;
            pos = true;
        } else {                               // steps -1.0, -1.5, ..., -60.5
            int u = s - 120;
            k0 = -(1 + (u >> 1)); k1 = k0 - 1;
            alpha = (u & 1) ? 0.5f : 0.0f;
            pos = false;
        }
        const float w0 = 1.0f - alpha, w1 = alpha;
        const float w00 = w0 * w0, w11 = w1 * w1, w01 = 2.0f * w0 * w1;
        float acc = 0.0f;
        #pragma unroll
        for (int t = 0; t < TI; t++) {
            int j0r = t + 60 - k0;             // window-relative row of roll k0
            int j1r = t + 60 - k1;
            float adot = pos ? sA[j0r] : sA[j1r];   // Q[j0].Q[j1] adjacency
            float x0 = Xs[t][k0 + 61];
            float x1 = Xs[t][k1 + 61];
            float r2 = sP2[t] + w00 * sQ2[j0r] + w11 * sQ2[j1r]
                     + w01 * adot - 2.0f * (w0 * x0 + w1 * x1);
            acc += sqrtf(fmaxf(r2, 0.0f));
        }
        g_bpart[s * NBLK + blockIdx.x] = acc;
    }

    // ---- Phase 4: last block reduces everything (no second launch) -----
    __threadfence();
    __shared__ bool is_last;
    __syncthreads();                 // all phase-3 stores of this block issued
    if (tid == 0) {
        unsigned t = atomicAdd(&g_ticket, 1u);
        is_last = (t == (unsigned)(NBLK - 1));
        if (is_last) g_ticket = 0;   // reset for next graph replay
    }
    __syncthreads();
    if (!is_last) return;

    // Deterministic mean + argmin (identical summation order every launch).
    const int s    = tid >> 1;       // 2 threads per step, 64 partials each
    const int half = tid & 1;
    unsigned long long key = ~0ull;
    if (s < NSTEPS) {
        const float4* bp = (const float4*)(g_bpart + s * NBLK + half * (NBLK / 2));
        float s0 = 0.f, s1 = 0.f, s2 = 0.f, s3 = 0.f;
        #pragma unroll
        for (int c = 0; c < NBLK / 8; c += 4) {
            float4 v0 = bp[c], v1 = bp[c + 1], v2 = bp[c + 2], v3 = bp[c + 3];
            s0 += v0.x + v0.y + v0.z + v0.w;
            s1 += v1.x + v1.y + v1.z + v1.w;
            s2 += v2.x + v2.y + v2.z + v2.w;
            s3 += v3.x + v3.y + v3.z + v3.w;
        }
        float mine = (s0 + s1) + (s2 + s3);
        float tot  = mine + __shfl_xor_sync(0xffffffffu, mine, 1);
        float dist = tot * (1.0f / (float)N_BINS);
        // positive-float bit order == numeric order; low 32 bits = index so
        // ties resolve to the smallest step index (matches jnp.argmin).
        key = ((unsigned long long)__float_as_uint(dist) << 32) | (unsigned)s;
    }
    #pragma unroll
    for (int off = 16; off; off >>= 1) {
        unsigned long long o = __shfl_xor_sync(0xffffffffu, key, off);
        if (o < key) key = o;
    }
    __shared__ unsigned long long wk[NWARPS];
    if (lane == 0) wk[warp] = key;
    __syncthreads();
    if (tid == 0) {
        unsigned long long best = wk[0];
        #pragma unroll
        for (int w = 1; w < NWARPS; w++) if (wk[w] < best) best = wk[w];
        int bi = (int)(best & 0xffffffffull);
        float dist = __uint_as_float((unsigned)(best >> 32));
        float step = (bi < 120) ? 0.5f * (float)bi : -(1.0f + 0.5f * (float)(bi - 120));
        out[0] = step;
        out[1] = dist;
    }
}

extern "C" void kernel_launch(void* const* d_in, const int* in_sizes, int n_in,
                              void* d_out, int out_size) {
    const float* Dq = (const float*)d_in[0];  // D_q [1024, 512]
    const float* Dp = (const float*)d_in[1];  // D_p [1024, 512]
    float* out = (float*)d_out;

    k_main<<<NBLK, NTHREADS>>>(Dq, Dp, out);
}